// round 1
// baseline (speedup 1.0000x reference)
#include <cuda_runtime.h>

// Inputs (metadata order): z [8192*128] f32 (UNUSED), risk [B] f32, time [B] f32, event [B] i32.
// Output: single f32 scalar = mean hinge over pairs (time[i]<time[j] && event[i]==1).

#define B_MAX 8192
#define TPB   256
#define ITI   2
#define I_PB  (TPB * ITI)   // 512 i's per block
#define JCH   512           // j's per block (smem chunk)

__device__ float2 g_ci[B_MAX];   // compacted (risk[i]+1, time[i]) for event[i]==1
__device__ int    g_ne;
__device__ double g_total;
__device__ double g_count;

__global__ void k_zero() {
    g_total = 0.0;
    g_count = 0.0;
}

// Deterministic single-block compaction: per-thread count -> shared scan -> ordered write.
__global__ __launch_bounds__(TPB) void k_compact(const float* __restrict__ risk,
                                                 const float* __restrict__ time_,
                                                 const int*   __restrict__ event,
                                                 int n) {
    __shared__ int cnt[TPB];
    int tid = threadIdx.x;
    int per = (n + TPB - 1) / TPB;
    int beg = tid * per;
    int end = beg + per; if (end > n) end = n;

    int c = 0;
    for (int i = beg; i < end; i++) c += (event[i] == 1);
    cnt[tid] = c;
    __syncthreads();

    // Hillis-Steele inclusive scan
    for (int off = 1; off < TPB; off <<= 1) {
        int v = cnt[tid];
        int add = (tid >= off) ? cnt[tid - off] : 0;
        __syncthreads();
        cnt[tid] = v + add;
        __syncthreads();
    }
    int excl = cnt[tid] - c;

    int p = excl;
    for (int i = beg; i < end; i++) {
        if (event[i] == 1) {
            g_ci[p] = make_float2(risk[i] + 1.0f, time_[i]);
            p++;
        }
    }
    if (tid == 0) g_ne = cnt[TPB - 1];
}

__global__ __launch_bounds__(TPB) void k_pairs(const float* __restrict__ risk,
                                               const float* __restrict__ time_,
                                               int n) {
    __shared__ float2 sj[JCH];
    __shared__ float  ssum[TPB];
    __shared__ int    scnt[TPB];

    const int tid = threadIdx.x;
    const int j0  = blockIdx.y * JCH;

    // Load this block's j-chunk into shared as (risk, time) pairs.
    for (int k = tid; k < JCH; k += TPB) {
        int j = j0 + k;
        if (j < n) {
            sj[k] = make_float2(risk[j], time_[j]);
        } else {
            // time=-1 < every ti -> never contributes
            sj[k] = make_float2(0.0f, -1.0f);
        }
    }
    __syncthreads();

    const int ne    = g_ne;
    const int ibase = blockIdx.x * I_PB;

    float s = 0.0f;
    int   c = 0;

    if (ibase < ne) {   // block-uniform: skip tiles entirely past compacted count
        float ri1[ITI], ti[ITI];
        #pragma unroll
        for (int t = 0; t < ITI; t++) {
            int ii = ibase + tid + t * TPB;
            if (ii < ne) {
                float2 v = g_ci[ii];
                ri1[t] = v.x;
                ti[t]  = v.y;
            } else {
                ri1[t] = 0.0f;
                ti[t]  = 3.0f;  // time in [0,1) -> tj > 3 never true -> inert lane
            }
        }

        #pragma unroll 8
        for (int k = 0; k < JCH; k++) {
            float2 v = sj[k];
            float rj = v.x, tj = v.y;
            #pragma unroll
            for (int t = 0; t < ITI; t++) {
                if (tj > ti[t]) {
                    s += fmaxf(ri1[t] - rj, 0.0f);
                    c += 1;
                }
            }
        }
    }

    // block reduction
    ssum[tid] = s;
    scnt[tid] = c;
    __syncthreads();
    for (int off = TPB / 2; off >= 1; off >>= 1) {
        if (tid < off) {
            ssum[tid] += ssum[tid + off];
            scnt[tid] += scnt[tid + off];
        }
        __syncthreads();
    }
    if (tid == 0) {
        atomicAdd(&g_total, (double)ssum[0]);
        atomicAdd(&g_count, (double)scnt[0]);
    }
}

__global__ void k_final(float* out) {
    double cnt = g_count;
    out[0] = (cnt == 0.0) ? 0.0f : (float)(g_total / cnt);
}

extern "C" void kernel_launch(void* const* d_in, const int* in_sizes, int n_in,
                              void* d_out, int out_size) {
    // d_in[0] = z (unused), d_in[1] = risk, d_in[2] = time, d_in[3] = event
    const float* risk  = (const float*)d_in[1];
    const float* time_ = (const float*)d_in[2];
    const int*   event = (const int*)d_in[3];
    const int n = in_sizes[1];

    k_zero<<<1, 1>>>();
    k_compact<<<1, TPB>>>(risk, time_, event, n);

    dim3 grid((n + I_PB - 1) / I_PB, (n + JCH - 1) / JCH);
    k_pairs<<<grid, TPB>>>(risk, time_, n);

    k_final<<<1, 1>>>((float*)d_out);
}

// round 2
// speedup vs baseline: 1.9250x; 1.9250x over previous
#include <cuda_runtime.h>

// Inputs (metadata order): z [8192*128] f32 (UNUSED), risk [B] f32, time [B] f32, event [B] i32.
// Output: single f32 scalar = mean hinge over pairs (time[i] < time[j] && event[i]==1).
//
// Single fused kernel:
//   - 2D grid of (i-tile, j-chunk) blocks
//   - each block compacts its own 512-row i-tile by event==1 into smem (block scan)
//   - issue-bound masked pair loop over a 512-entry smem j-chunk
//   - double atomics into device globals; last block finalizes AND resets globals
//     (replay-idempotent: safe under CUDA graph capture/replay)

#define TPB    256
#define I_TILE 512
#define JCH    512
#define NWARPS (TPB / 32)

__device__ double       g_total;   // zero-initialized at module load; reset by last block
__device__ double       g_count;
__device__ unsigned int g_done;

__global__ __launch_bounds__(TPB) void k_fused(const float* __restrict__ risk,
                                               const float* __restrict__ time_,
                                               const int*   __restrict__ event,
                                               float*       __restrict__ out,
                                               int n, unsigned int nblocks) {
    __shared__ float2 sj[JCH];       // (risk_j, time_j)
    __shared__ float2 sci[I_TILE];   // compacted (risk_i + 1, time_i) for event==1
    __shared__ int    sscan[TPB];
    __shared__ int    s_ne;
    __shared__ float  swsum[NWARPS];
    __shared__ int    swcnt[NWARPS];

    const int tid = threadIdx.x;
    const int i0  = blockIdx.x * I_TILE;
    const int j0  = blockIdx.y * JCH;

    // ---- load j-chunk into shared ----
    #pragma unroll
    for (int k = tid; k < JCH; k += TPB) {
        int j = j0 + k;
        float rj = 0.0f, tj = -1.0f;     // tj=-1 < any real time -> never contributes
        if (j < n) { rj = risk[j]; tj = time_[j]; }
        sj[k] = make_float2(rj, tj);
    }

    // ---- per-block compaction of this i-tile (event==1), deterministic order ----
    int ia = i0 + 2 * tid;
    int ib = ia + 1;
    int ea = (ia < n) && (event[ia] == 1);
    int eb = (ib < n) && (event[ib] == 1);
    float ra = 0.f, ta = 0.f, rb = 0.f, tb = 0.f;
    if (ea) { ra = risk[ia] + 1.0f; ta = time_[ia]; }
    if (eb) { rb = risk[ib] + 1.0f; tb = time_[ib]; }
    int cloc = ea + eb;
    sscan[tid] = cloc;
    __syncthreads();
    // Hillis-Steele inclusive scan over 256 threads
    #pragma unroll
    for (int off = 1; off < TPB; off <<= 1) {
        int v   = sscan[tid];
        int add = (tid >= off) ? sscan[tid - off] : 0;
        __syncthreads();
        sscan[tid] = v + add;
        __syncthreads();
    }
    {
        int pos = sscan[tid] - cloc;
        if (ea) { sci[pos] = make_float2(ra, ta); pos++; }
        if (eb) { sci[pos] = make_float2(rb, tb); }
        if (tid == TPB - 1) s_ne = sscan[TPB - 1];
    }
    __syncthreads();
    const int ne = s_ne;

    // ---- pair loop: thread owns compacted rows {tid, tid+256} ----
    float s0 = 0.f, s1 = 0.f;
    int   c0 = 0,   c1 = 0;

    if (tid + TPB < ne) {
        // two active i's
        float2 u0 = sci[tid];
        float2 u1 = sci[tid + TPB];
        const float r01 = u0.x, t0 = u0.y;
        const float r11 = u1.x, t1 = u1.y;
        #pragma unroll 8
        for (int k = 0; k < JCH; k++) {
            float2 v = sj[k];
            if (v.y > t0) { s0 += fmaxf(r01 - v.x, 0.0f); c0++; }
            if (v.y > t1) { s1 += fmaxf(r11 - v.x, 0.0f); c1++; }
        }
    } else if (tid < ne) {
        // one active i
        float2 u0 = sci[tid];
        const float r01 = u0.x, t0 = u0.y;
        #pragma unroll 8
        for (int k = 0; k < JCH; k++) {
            float2 v = sj[k];
            if (v.y > t0) { s0 += fmaxf(r01 - v.x, 0.0f); c0++; }
        }
    }

    // ---- reduction: warp shfl -> smem -> warp0 -> atomics ----
    float s = s0 + s1;
    int   c = c0 + c1;
    #pragma unroll
    for (int off = 16; off >= 1; off >>= 1) {
        s += __shfl_down_sync(0xffffffffu, s, off);
        c += __shfl_down_sync(0xffffffffu, c, off);
    }
    if ((tid & 31) == 0) { swsum[tid >> 5] = s; swcnt[tid >> 5] = c; }
    __syncthreads();
    if (tid < NWARPS) {
        s = swsum[tid];
        c = swcnt[tid];
        #pragma unroll
        for (int off = NWARPS / 2; off >= 1; off >>= 1) {
            s += __shfl_down_sync((1u << NWARPS) - 1u, s, off);
            c += __shfl_down_sync((1u << NWARPS) - 1u, c, off);
        }
        if (tid == 0) {
            if (s != 0.0f || c != 0) {
                atomicAdd(&g_total, (double)s);
                atomicAdd(&g_count, (double)c);
            }
            __threadfence();
            unsigned int prev = atomicAdd(&g_done, 1u);
            if (prev == nblocks - 1) {
                // all blocks' atomics are visible (fence before each done-increment)
                __threadfence();
                double tt = atomicAdd(&g_total, 0.0);
                double cc = atomicAdd(&g_count, 0.0);
                out[0] = (cc == 0.0) ? 0.0f : (float)(tt / cc);
                // reset for next graph replay (idempotent kernel)
                g_total = 0.0;
                g_count = 0.0;
                g_done  = 0u;
            }
        }
    }
}

extern "C" void kernel_launch(void* const* d_in, const int* in_sizes, int n_in,
                              void* d_out, int out_size) {
    // d_in[0] = z (unused), d_in[1] = risk, d_in[2] = time, d_in[3] = event
    const float* risk  = (const float*)d_in[1];
    const float* time_ = (const float*)d_in[2];
    const int*   event = (const int*)d_in[3];
    const int n = in_sizes[1];

    dim3 grid((n + I_TILE - 1) / I_TILE, (n + JCH - 1) / JCH);
    unsigned int nblocks = grid.x * grid.y;

    k_fused<<<grid, TPB>>>(risk, time_, event, (float*)d_out, n, nblocks);
}